// round 15
// baseline (speedup 1.0000x reference)
#include <cuda_runtime.h>
#include <cuda_bf16.h>
#include <cstdint>

#define DI __device__ __forceinline__

namespace {
constexpr int S = 16384;      // tokens = 16*32*32
constexpr int C = 128;        // channels
constexpr int NUNITS = 2176;  // (64-row tile, 1024-key span) units, uniform
// (1/sqrt(128)) * log2(e): folded into Q so softmax uses exp2
constexpr float SCALE_LOG2E = 0.08838834764831845f * 1.4426950408889634f;
}

// units before frame f: 8*f*(f+1)  (frame f has 16 tiles * (f+1) splits)
__constant__ int cU2[17] = {0,16,48,96,160,240,336,448,576,720,880,1056,
                            1248,1456,1680,1920,2176};

// ---------------- scratch (device globals; no allocs allowed) ----------------
__device__ __align__(128) __nv_bfloat16 g_xn[S * C];
__device__ __align__(128) __nv_bfloat16 g_q [S * C];
__device__ __align__(128) __nv_bfloat16 g_k [S * C];
__device__ __align__(128) __nv_bfloat16 g_v [S * C];
__device__ __align__(128) __nv_bfloat16 g_at[S * C];
__device__ __align__(128) __nv_bfloat16 g_wt[4][C * C];        // wt[n][k] = W[k][n]
__device__ __align__(128) __nv_bfloat16 g_po[(size_t)NUNITS * 8192]; // partial O (bf16, 64x128)
__device__ __align__(128) float g_pl[NUNITS * 64];             // partial l per row

// ---------------- small PTX helpers ----------------
DI uint32_t sptr(const void* p) { return (uint32_t)__cvta_generic_to_shared(p); }
DI void cp16(uint32_t s, const void* g) {
    asm volatile("cp.async.cg.shared.global [%0], [%1], 16;\n" :: "r"(s), "l"(g));
}
DI void cp_commit() { asm volatile("cp.async.commit_group;\n" ::: "memory"); }
template<int N> DI void cp_wait() { asm volatile("cp.async.wait_group %0;\n" :: "n"(N) : "memory"); }
DI float ex2(float x) { float y; asm("ex2.approx.f32 %0, %1;" : "=f"(y) : "f"(x)); return y; }

// tile layout: rows x 128 bf16 (256B/row, 16 chunks of 16B), XOR-swizzled
DI uint32_t sw_off(int row, int ch) { return (uint32_t)(row * 256 + ((ch ^ (row & 7)) << 4)); }

DI void ldsm4(uint32_t* r, uint32_t a) {
    asm volatile("ldmatrix.sync.aligned.m8n8.x4.shared.b16 {%0,%1,%2,%3}, [%4];\n"
                 : "=r"(r[0]), "=r"(r[1]), "=r"(r[2]), "=r"(r[3]) : "r"(a));
}
DI void ldsm4t(uint32_t* r, uint32_t a) {
    asm volatile("ldmatrix.sync.aligned.m8n8.x4.trans.shared.b16 {%0,%1,%2,%3}, [%4];\n"
                 : "=r"(r[0]), "=r"(r[1]), "=r"(r[2]), "=r"(r[3]) : "r"(a));
}
DI void mma16816(float* d, const uint32_t* a, const uint32_t* b) {
    asm volatile("mma.sync.aligned.m16n8k16.row.col.f32.bf16.bf16.f32 "
                 "{%0,%1,%2,%3}, {%4,%5,%6,%7}, {%8,%9}, {%0,%1,%2,%3};\n"
                 : "+f"(d[0]), "+f"(d[1]), "+f"(d[2]), "+f"(d[3])
                 : "r"(a[0]), "r"(a[1]), "r"(a[2]), "r"(a[3]), "r"(b[0]), "r"(b[1]));
}
DI uint32_t packbf(float lo, float hi) {
    __nv_bfloat162 t = __floats2bfloat162_rn(lo, hi);
    return *reinterpret_cast<uint32_t*>(&t);
}

// async copy of an [R x 128] bf16 row-major tile into swizzled smem
template<int R, int NT>
DI void load_tile(uint32_t sbase, const __nv_bfloat16* g, int tid) {
#pragma unroll
    for (int i = 0; i < (R * 16) / NT; i++) {
        int idx = tid + i * NT;
        int row = idx >> 4, ch = idx & 15;
        cp16(sbase + sw_off(row, ch), g + row * 128 + ch * 8);
    }
}

// ---------------- 1) RMSNorm -> bf16 xn ----------------
__global__ void __launch_bounds__(256) k_norm(const float* __restrict__ x,
                                              const float* __restrict__ gamma) {
    int token = blockIdx.x * 8 + (threadIdx.x >> 5);
    int lane  = threadIdx.x & 31;
    float4 a = reinterpret_cast<const float4*>(x + token * 128)[lane];
    float ss = a.x * a.x + a.y * a.y + a.z * a.z + a.w * a.w;
#pragma unroll
    for (int m = 16; m; m >>= 1) ss += __shfl_xor_sync(0xffffffffu, ss, m);
    float sc = 11.313708498984761f / (sqrtf(ss) + 1e-8f);
    float4 gv = reinterpret_cast<const float4*>(gamma)[lane];
    __nv_bfloat162* o = reinterpret_cast<__nv_bfloat162*>(g_xn + token * 128) + lane * 2;
    o[0] = __floats2bfloat162_rn(a.x * sc * gv.x, a.y * sc * gv.y);
    o[1] = __floats2bfloat162_rn(a.z * sc * gv.z, a.w * sc * gv.w);
}

// ---------------- 2) weight transpose + bf16 convert ----------------
__global__ void __launch_bounds__(256) k_wconv(const float* __restrict__ wq,
                                               const float* __restrict__ wk,
                                               const float* __restrict__ wv,
                                               const float* __restrict__ wo) {
    const float* src = blockIdx.y == 0 ? wq : blockIdx.y == 1 ? wk
                     : blockIdx.y == 2 ? wv : wo;
    int idx = blockIdx.x * 256 + threadIdx.x;
    int n = idx >> 7, k = idx & 127;
    g_wt[blockIdx.y][idx] = __float2bfloat16(src[k * 128 + n]);
}

// ---------------- 3) QKV projection GEMM (bf16 mma) ----------------
__global__ void __launch_bounds__(256) k_qkv(const float* __restrict__ bq,
                                             const float* __restrict__ bk,
                                             const float* __restrict__ bv) {
    extern __shared__ __align__(1024) char smem[];
    uint32_t sA = sptr(smem), sB = sA + 128 * 256;
    int which = blockIdx.y;
    int tid = threadIdx.x, wid = tid >> 5, lane = tid & 31;
    load_tile<128, 256>(sA, g_xn + blockIdx.x * 128 * 128, tid);
    load_tile<128, 256>(sB, g_wt[which], tid);
    cp_commit(); cp_wait<0>(); __syncthreads();
    int agrp = lane >> 3, lr = lane & 7;
    int mrow = wid * 16 + lr + ((agrp & 1) << 3);
    float acc[16][4];
#pragma unroll
    for (int i = 0; i < 16; i++) { acc[i][0] = acc[i][1] = acc[i][2] = acc[i][3] = 0.f; }
#pragma unroll
    for (int kk2 = 0; kk2 < 4; kk2++) {
        uint32_t a0[4], a1[4];
        ldsm4(a0, sA + sw_off(mrow, 4 * kk2 +     (agrp >> 1)));
        ldsm4(a1, sA + sw_off(mrow, 4 * kk2 + 2 + (agrp >> 1)));
#pragma unroll
        for (int nt = 0; nt < 16; nt++) {
            uint32_t b[4];
            ldsm4(b, sB + sw_off(nt * 8 + lr, 4 * kk2 + agrp));
            mma16816(acc[nt], a0, b);
            mma16816(acc[nt], a1, b + 2);
        }
    }
    const float* bias = which == 0 ? bq : which == 1 ? bk : bv;
    __nv_bfloat16* out = which == 0 ? g_q : which == 1 ? g_k : g_v;
    float mul = (which == 0) ? SCALE_LOG2E : 1.0f;   // fold softmax scale into Q
    int r0 = blockIdx.x * 128 + wid * 16 + (lane >> 2);
    int cb = (lane & 3) * 2;
#pragma unroll
    for (int nt = 0; nt < 16; nt++) {
        int col = nt * 8 + cb;
        float b0 = bias[col], b1 = bias[col + 1];
        *reinterpret_cast<__nv_bfloat162*>(out + (size_t)r0 * 128 + col) =
            __floats2bfloat162_rn((acc[nt][0] + b0) * mul, (acc[nt][1] + b1) * mul);
        *reinterpret_cast<__nv_bfloat162*>(out + (size_t)(r0 + 8) * 128 + col) =
            __floats2bfloat162_rn((acc[nt][2] + b0) * mul, (acc[nt][3] + b1) * mul);
    }
}

// ---------------- 4) split-KV flash attention (3 CTAs/SM, 32-key chunks) ----------------
// Unit = (64-row Q-tile, 1024 keys = 32 chunks of 32). 4 warps x m16, Q in regs,
// ring-3 K/V (8KB each), fixed-max softmax. smem 64KB -> 3 CTAs/SM = 12 warps/SM.
__global__ void __launch_bounds__(128, 3) k_attn() {
    extern __shared__ __align__(1024) char smem[];
    uint32_t sQ = sptr(smem);
    uint32_t sK[3], sV[3];
#pragma unroll
    for (int st = 0; st < 3; st++) {
        sK[st] = sQ + 16384 + st * 16384;
        sV[st] = sK[st] + 8192;
    }
    int tid = threadIdx.x, wid = tid >> 5, lane = tid & 31;
    int agrp = lane >> 3, lr = lane & 7;

    int u = NUNITS - 1 - (int)blockIdx.x;
    int f = 0;
#pragma unroll
    for (int i = 0; i < 16; i++) if (u >= cU2[i + 1]) f = i + 1;
    int r   = u - cU2[f];
    int ns  = f + 1;
    int tif = r / ns;
    int sp  = r - tif * ns;
    int q0  = (f * 16 + tif) * 64;
    int kc0 = sp * 32;                    // 32 chunks of 32 keys (always full)

    // prologue: G0 = {Q, K0, V0}, G1 = {K1, V1}
    load_tile<64, 128>(sQ, g_q + (size_t)q0 * 128, tid);
    load_tile<32, 128>(sK[0], g_k + (size_t)kc0 * 4096, tid);
    load_tile<32, 128>(sV[0], g_v + (size_t)kc0 * 4096, tid);
    cp_commit();
    load_tile<32, 128>(sK[1], g_k + (size_t)(kc0 + 1) * 4096, tid);
    load_tile<32, 128>(sV[1], g_v + (size_t)(kc0 + 1) * 4096, tid);
    cp_commit();
    cp_wait<1>();
    __syncthreads();

    int mrow = wid * 16 + lr + ((agrp & 1) << 3);
    uint32_t qf[8][4];                     // Q cached in registers
#pragma unroll
    for (int kk = 0; kk < 8; kk++)
        ldsm4(qf[kk], sQ + sw_off(mrow, 2 * kk + (agrp >> 1)));

    float o[16][4];
#pragma unroll
    for (int j = 0; j < 16; j++) { o[j][0] = o[j][1] = o[j][2] = o[j][3] = 0.f; }
    float l0 = 0.f, l1 = 0.f;

    for (int i = 0; i < 32; i++) {
        __syncthreads();                   // all warps done with slot (i+2)%3
        if (i + 2 < 32) {
            int st = (i + 2) % 3;
            load_tile<32, 128>(sK[st], g_k + (size_t)(kc0 + i + 2) * 4096, tid);
            load_tile<32, 128>(sV[st], g_v + (size_t)(kc0 + i + 2) * 4096, tid);
        }
        cp_commit();
        cp_wait<1>();                      // chunk i+1 resident (i already resident)
        uint32_t kb = sK[i % 3], vb = sV[i % 3];

        // ---- S = Q @ K^T : 16 rows x 32 keys ----
        float s[4][4];
#pragma unroll
        for (int nt = 0; nt < 4; nt++) { s[nt][0] = s[nt][1] = s[nt][2] = s[nt][3] = 0.f; }
#pragma unroll
        for (int kk2 = 0; kk2 < 4; kk2++) {
#pragma unroll
            for (int nt = 0; nt < 4; nt++) {
                uint32_t b[4];
                ldsm4(b, kb + sw_off(nt * 8 + lr, 4 * kk2 + agrp));
                mma16816(s[nt], qf[2 * kk2],     b);
                mma16816(s[nt], qf[2 * kk2 + 1], b + 2);
            }
        }

        // ---- fixed-max softmax -> bf16 A-fragments ----
        uint32_t pf[2][4];
#pragma unroll
        for (int nt = 0; nt < 4; nt++) {
            float p0 = ex2(s[nt][0]);
            float p1 = ex2(s[nt][1]);
            float p2 = ex2(s[nt][2]);
            float p3 = ex2(s[nt][3]);
            l0 += p0 + p1;  l1 += p2 + p3;
            int kk = nt >> 1;
            if ((nt & 1) == 0) { pf[kk][0] = packbf(p0, p1); pf[kk][1] = packbf(p2, p3); }
            else               { pf[kk][2] = packbf(p0, p1); pf[kk][3] = packbf(p2, p3); }
        }

        // ---- O += P @ V (k=32) ----
#pragma unroll
        for (int j = 0; j < 16; j++) {
            uint32_t vv[4];
            ldsm4t(vv, vb + sw_off(agrp * 8 + lr, j));
            mma16816(o[j], pf[0], vv);
            mma16816(o[j], pf[1], vv + 2);
        }
    }

    // ---- epilogue: quad-reduce l, store unnormalized partials (bf16) ----
    l0 += __shfl_xor_sync(0xffffffffu, l0, 1);
    l0 += __shfl_xor_sync(0xffffffffu, l0, 2);
    l1 += __shfl_xor_sync(0xffffffffu, l1, 1);
    l1 += __shfl_xor_sync(0xffffffffu, l1, 2);
    int lr0 = wid * 16 + (lane >> 2);
    int cb  = (lane & 3) * 2;
    __nv_bfloat16* po = g_po + (size_t)u * 8192;
#pragma unroll
    for (int j = 0; j < 16; j++) {
        int col = j * 8 + cb;
        *reinterpret_cast<__nv_bfloat162*>(po + (size_t)lr0 * 128 + col) =
            __floats2bfloat162_rn(o[j][0], o[j][1]);
        *reinterpret_cast<__nv_bfloat162*>(po + (size_t)(lr0 + 8) * 128 + col) =
            __floats2bfloat162_rn(o[j][2], o[j][3]);
    }
    if ((lane & 3) == 0) {
        g_pl[u * 64 + lr0]     = l0;
        g_pl[u * 64 + lr0 + 8] = l1;
    }
}

// ---------------- 4b) combine (plain sums over bf16 partials) ----------------
// grid 256: one block per 64-row tile.
__global__ void __launch_bounds__(256) k_comb() {
    int t  = blockIdx.x;
    int f  = t >> 4;
    int ns = f + 1;
    int ub = cU2[f] + (t & 15) * ns;
    int row = threadIdx.x >> 2;
    int c0  = (threadIdx.x & 3) * 32;
    float l = 0.f;
    for (int s = 0; s < ns; s++) l += g_pl[(ub + s) * 64 + row];
    float inv = 1.f / l;
    float acc[32];
#pragma unroll
    for (int j = 0; j < 32; j++) acc[j] = 0.f;
    for (int s = 0; s < ns; s++) {
        const __nv_bfloat162* p = reinterpret_cast<const __nv_bfloat162*>(
            g_po + (size_t)(ub + s) * 8192 + (size_t)row * 128 + c0);
#pragma unroll
        for (int j = 0; j < 16; j++) {
            float2 v = __bfloat1622float2(p[j]);
            acc[2 * j] += v.x;  acc[2 * j + 1] += v.y;
        }
    }
    __nv_bfloat162* dst = reinterpret_cast<__nv_bfloat162*>(
        g_at + (size_t)(t * 64 + row) * 128 + c0);
#pragma unroll
    for (int j = 0; j < 16; j++)
        dst[j] = __floats2bfloat162_rn(acc[2 * j] * inv, acc[2 * j + 1] * inv);
}

// ---------------- 5) output projection + bias + residual ----------------
__global__ void __launch_bounds__(256) k_oproj(const float* __restrict__ bo,
                                               const float* __restrict__ x,
                                               float* __restrict__ out) {
    extern __shared__ __align__(1024) char smem[];
    uint32_t sA = sptr(smem), sB = sA + 128 * 256;
    int tid = threadIdx.x, wid = tid >> 5, lane = tid & 31;
    load_tile<128, 256>(sA, g_at + blockIdx.x * 128 * 128, tid);
    load_tile<128, 256>(sB, g_wt[3], tid);
    cp_commit(); cp_wait<0>(); __syncthreads();
    int agrp = lane >> 3, lr = lane & 7;
    int mrow = wid * 16 + lr + ((agrp & 1) << 3);
    float acc[16][4];
#pragma unroll
    for (int i = 0; i < 16; i++) { acc[i][0] = acc[i][1] = acc[i][2] = acc[i][3] = 0.f; }
#pragma unroll
    for (int kk2 = 0; kk2 < 4; kk2++) {
        uint32_t a0[4], a1[4];
        ldsm4(a0, sA + sw_off(mrow, 4 * kk2 +     (agrp >> 1)));
        ldsm4(a1, sA + sw_off(mrow, 4 * kk2 + 2 + (agrp >> 1)));
#pragma unroll
        for (int nt = 0; nt < 16; nt++) {
            uint32_t b[4];
            ldsm4(b, sB + sw_off(nt * 8 + lr, 4 * kk2 + agrp));
            mma16816(acc[nt], a0, b);
            mma16816(acc[nt], a1, b + 2);
        }
    }
    int r0 = blockIdx.x * 128 + wid * 16 + (lane >> 2);
    int cb = (lane & 3) * 2;
#pragma unroll
    for (int nt = 0; nt < 16; nt++) {
        int col = nt * 8 + cb;
        float b0 = bo[col], b1 = bo[col + 1];
        *reinterpret_cast<float2*>(out + r0 * 128 + col) =
            make_float2(acc[nt][0] + b0 + x[r0 * 128 + col],
                        acc[nt][1] + b1 + x[r0 * 128 + col + 1]);
        *reinterpret_cast<float2*>(out + (r0 + 8) * 128 + col) =
            make_float2(acc[nt][2] + b0 + x[(r0 + 8) * 128 + col],
                        acc[nt][3] + b1 + x[(r0 + 8) * 128 + col + 1]);
    }
}

// ---------------- launch ----------------
extern "C" void kernel_launch(void* const* d_in, const int* in_sizes, int n_in,
                              void* d_out, int out_size) {
    (void)in_sizes; (void)n_in; (void)out_size;
    const float* x     = (const float*)d_in[0];
    const float* gamma = (const float*)d_in[1];
    const float* wq = (const float*)d_in[2];
    const float* bq = (const float*)d_in[3];
    const float* wk = (const float*)d_in[4];
    const float* bk = (const float*)d_in[5];
    const float* wv = (const float*)d_in[6];
    const float* bv = (const float*)d_in[7];
    const float* wo = (const float*)d_in[8];
    const float* bo = (const float*)d_in[9];
    float* out = (float*)d_out;

    cudaFuncSetAttribute(k_qkv,   cudaFuncAttributeMaxDynamicSharedMemorySize, 65536);
    cudaFuncSetAttribute(k_oproj, cudaFuncAttributeMaxDynamicSharedMemorySize, 65536);
    cudaFuncSetAttribute(k_attn,  cudaFuncAttributeMaxDynamicSharedMemorySize, 65536);

    k_norm <<<S / 8, 256>>>(x, gamma);
    k_wconv<<<dim3(64, 4), 256>>>(wq, wk, wv, wo);
    k_qkv  <<<dim3(S / 128, 3), 256, 65536>>>(bq, bk, bv);
    k_attn <<<NUNITS, 128, 65536>>>();
    k_comb <<<256, 256>>>();
    k_oproj<<<S / 128, 256, 65536>>>(bo, x, out);
}

// round 17
// speedup vs baseline: 1.2434x; 1.2434x over previous
#include <cuda_runtime.h>
#include <cuda_bf16.h>
#include <cstdint>

#define DI __device__ __forceinline__

namespace {
constexpr int S = 16384;      // tokens = 16*32*32
constexpr int C = 128;        // channels
constexpr int NU = 2176;      // (64-row tile, 1024-key span) units, uniform
// (1/sqrt(128)) * log2(e): folded into Q so softmax uses exp2
constexpr float SCALE_LOG2E = 0.08838834764831845f * 1.4426950408889634f;
constexpr int SM_ATTN = 98304 + 64;   // 3x(16K K +16K V) slots + mbarriers
}

// units before frame f: 8*f*(f+1)  (frame f has 16 tiles * (f+1) splits)
__constant__ int cU2[17] = {0,16,48,96,160,240,336,448,576,720,880,1056,
                            1248,1456,1680,1920,2176};

// ---------------- scratch (device globals; no allocs allowed) ----------------
__device__ __align__(128) __nv_bfloat16 g_xn[S * C];
__device__ __align__(128) __nv_bfloat16 g_q [S * C];          // linear layout
__device__ __align__(128) __nv_bfloat16 g_k [S * C];          // PRE-SWIZZLED 64-row chunks
__device__ __align__(128) __nv_bfloat16 g_v [S * C];          // PRE-SWIZZLED 64-row chunks
__device__ __align__(128) __nv_bfloat16 g_at[S * C];
__device__ __align__(128) __nv_bfloat16 g_wt[4][C * C];       // wt[n][k] = W[k][n]
__device__ __align__(128) __nv_bfloat16 g_po[(size_t)NU * 8192]; // partial O (bf16, 64x128)
__device__ __align__(128) float g_pl[NU * 64];                // partial l per row

// ---------------- small PTX helpers ----------------
DI uint32_t sptr(const void* p) { return (uint32_t)__cvta_generic_to_shared(p); }
DI void cp16(uint32_t s, const void* g) {
    asm volatile("cp.async.cg.shared.global [%0], [%1], 16;\n" :: "r"(s), "l"(g));
}
DI void cp_commit() { asm volatile("cp.async.commit_group;\n" ::: "memory"); }
template<int N> DI void cp_wait() { asm volatile("cp.async.wait_group %0;\n" :: "n"(N) : "memory"); }
DI float ex2(float x) { float y; asm("ex2.approx.f32 %0, %1;" : "=f"(y) : "f"(x)); return y; }
DI bool elect1() {
    uint32_t p;
    asm volatile("{\n\t.reg .pred p;\n\telect.sync _|p, 0xFFFFFFFF;\n\tselp.b32 %0,1,0,p;\n\t}"
                 : "=r"(p));
    return p != 0;
}
DI void mbar_init(uint32_t a, uint32_t c) {
    asm volatile("mbarrier.init.shared.b64 [%0], %1;\n" :: "r"(a), "r"(c) : "memory");
}
DI void mbar_wait(uint32_t a, uint32_t par) {
    asm volatile("{\n\t.reg .pred P;\n\tW%=:\n\t"
                 "mbarrier.try_wait.parity.acquire.cta.shared::cta.b64 P, [%0], %1, 0x989680;\n\t"
                 "@!P bra W%=;\n\t}" :: "r"(a), "r"(par) : "memory");
}
DI void mbar_arrive(uint32_t a) {
    asm volatile("mbarrier.arrive.shared.b64 _, [%0];\n" :: "r"(a) : "memory");
}
DI void mbar_expect(uint32_t a, uint32_t n) {
    asm volatile("mbarrier.arrive.expect_tx.shared.b64 _, [%0], %1;\n"
                 :: "r"(a), "r"(n) : "memory");
}
DI void bulk_g2s(uint32_t d, const void* s, uint32_t n, uint32_t mb) {
    asm volatile("cp.async.bulk.shared::cta.global.mbarrier::complete_tx::bytes "
                 "[%0], [%1], %2, [%3];\n" :: "r"(d), "l"(s), "r"(n), "r"(mb) : "memory");
}

// tile layout: rows x 128 bf16 (256B/row, 16 chunks of 16B), XOR-swizzled
DI uint32_t sw_off(int row, int ch) { return (uint32_t)(row * 256 + ((ch ^ (row & 7)) << 4)); }

DI void ldsm4(uint32_t* r, uint32_t a) {
    asm volatile("ldmatrix.sync.aligned.m8n8.x4.shared.b16 {%0,%1,%2,%3}, [%4];\n"
                 : "=r"(r[0]), "=r"(r[1]), "=r"(r[2]), "=r"(r[3]) : "r"(a));
}
DI void ldsm4t(uint32_t* r, uint32_t a) {
    asm volatile("ldmatrix.sync.aligned.m8n8.x4.trans.shared.b16 {%0,%1,%2,%3}, [%4];\n"
                 : "=r"(r[0]), "=r"(r[1]), "=r"(r[2]), "=r"(r[3]) : "r"(a));
}
DI void mma16816(float* d, const uint32_t* a, const uint32_t* b) {
    asm volatile("mma.sync.aligned.m16n8k16.row.col.f32.bf16.bf16.f32 "
                 "{%0,%1,%2,%3}, {%4,%5,%6,%7}, {%8,%9}, {%0,%1,%2,%3};\n"
                 : "+f"(d[0]), "+f"(d[1]), "+f"(d[2]), "+f"(d[3])
                 : "r"(a[0]), "r"(a[1]), "r"(a[2]), "r"(a[3]), "r"(b[0]), "r"(b[1]));
}
DI uint32_t packbf(float lo, float hi) {
    __nv_bfloat162 t = __floats2bfloat162_rn(lo, hi);
    return *reinterpret_cast<uint32_t*>(&t);
}

// async copy of an [R x 128] bf16 row-major tile into swizzled smem (proj kernels)
template<int R, int NT>
DI void load_tile(uint32_t sbase, const __nv_bfloat16* g, int tid) {
#pragma unroll
    for (int i = 0; i < (R * 16) / NT; i++) {
        int idx = tid + i * NT;
        int row = idx >> 4, ch = idx & 15;
        cp16(sbase + sw_off(row, ch), g + row * 128 + ch * 8);
    }
}

// ---------------- 1) RMSNorm -> bf16 xn ----------------
__global__ void __launch_bounds__(256) k_norm(const float* __restrict__ x,
                                              const float* __restrict__ gamma) {
    int token = blockIdx.x * 8 + (threadIdx.x >> 5);
    int lane  = threadIdx.x & 31;
    float4 a = reinterpret_cast<const float4*>(x + token * 128)[lane];
    float ss = a.x * a.x + a.y * a.y + a.z * a.z + a.w * a.w;
#pragma unroll
    for (int m = 16; m; m >>= 1) ss += __shfl_xor_sync(0xffffffffu, ss, m);
    float sc = 11.313708498984761f / (sqrtf(ss) + 1e-8f);
    float4 gv = reinterpret_cast<const float4*>(gamma)[lane];
    __nv_bfloat162* o = reinterpret_cast<__nv_bfloat162*>(g_xn + token * 128) + lane * 2;
    o[0] = __floats2bfloat162_rn(a.x * sc * gv.x, a.y * sc * gv.y);
    o[1] = __floats2bfloat162_rn(a.z * sc * gv.z, a.w * sc * gv.w);
}

// ---------------- 2) weight transpose + bf16 convert ----------------
__global__ void __launch_bounds__(256) k_wconv(const float* __restrict__ wq,
                                               const float* __restrict__ wk,
                                               const float* __restrict__ wv,
                                               const float* __restrict__ wo) {
    const float* src = blockIdx.y == 0 ? wq : blockIdx.y == 1 ? wk
                     : blockIdx.y == 2 ? wv : wo;
    int idx = blockIdx.x * 256 + threadIdx.x;
    int n = idx >> 7, k = idx & 127;
    g_wt[blockIdx.y][idx] = __float2bfloat16(src[k * 128 + n]);
}

// ---------------- 3) QKV projection GEMM (bf16 mma) ----------------
// Q written linear (scale folded); K/V written PRE-SWIZZLED in 64-row chunks so
// k_attn can bulk-copy them straight into ldsm-ready smem images.
__global__ void __launch_bounds__(256) k_qkv(const float* __restrict__ bq,
                                             const float* __restrict__ bk,
                                             const float* __restrict__ bv) {
    extern __shared__ __align__(1024) char smem[];
    uint32_t sA = sptr(smem), sB = sA + 128 * 256;
    int which = blockIdx.y;
    int tid = threadIdx.x, wid = tid >> 5, lane = tid & 31;
    load_tile<128, 256>(sA, g_xn + blockIdx.x * 128 * 128, tid);
    load_tile<128, 256>(sB, g_wt[which], tid);
    cp_commit(); cp_wait<0>(); __syncthreads();
    int agrp = lane >> 3, lr = lane & 7;
    int mrow = wid * 16 + lr + ((agrp & 1) << 3);
    float acc[16][4];
#pragma unroll
    for (int i = 0; i < 16; i++) { acc[i][0] = acc[i][1] = acc[i][2] = acc[i][3] = 0.f; }
#pragma unroll
    for (int kk2 = 0; kk2 < 4; kk2++) {
        uint32_t a0[4], a1[4];
        ldsm4(a0, sA + sw_off(mrow, 4 * kk2 +     (agrp >> 1)));
        ldsm4(a1, sA + sw_off(mrow, 4 * kk2 + 2 + (agrp >> 1)));
#pragma unroll
        for (int nt = 0; nt < 16; nt++) {
            uint32_t b[4];
            ldsm4(b, sB + sw_off(nt * 8 + lr, 4 * kk2 + agrp));
            mma16816(acc[nt], a0, b);
            mma16816(acc[nt], a1, b + 2);
        }
    }
    const float* bias = which == 0 ? bq : which == 1 ? bk : bv;
    int r0 = blockIdx.x * 128 + wid * 16 + (lane >> 2);
    int cb = (lane & 3) * 2;
#pragma unroll
    for (int nt = 0; nt < 16; nt++) {
        int col = nt * 8 + cb;
        float b0 = bias[col], b1 = bias[col + 1];
        float v00 = acc[nt][0] + b0, v01 = acc[nt][1] + b1;
        float v10 = acc[nt][2] + b0, v11 = acc[nt][3] + b1;
        if (which == 0) {
            *reinterpret_cast<uint32_t*>(g_q + (size_t)r0 * 128 + col) =
                packbf(v00 * SCALE_LOG2E, v01 * SCALE_LOG2E);
            *reinterpret_cast<uint32_t*>(g_q + (size_t)(r0 + 8) * 128 + col) =
                packbf(v10 * SCALE_LOG2E, v11 * SCALE_LOG2E);
        } else {
            char* outc = which == 1 ? (char*)g_k : (char*)g_v;
            int ra = r0, rb = r0 + 8;
            int ca = ra >> 6, rra = ra & 63;
            int cbk = rb >> 6, rrb = rb & 63;
            *reinterpret_cast<uint32_t*>(outc + (size_t)ca * 16384 + rra * 256 +
                ((uint32_t)(nt ^ (rra & 7)) << 4) + cb * 2) = packbf(v00, v01);
            *reinterpret_cast<uint32_t*>(outc + (size_t)cbk * 16384 + rrb * 256 +
                ((uint32_t)(nt ^ (rrb & 7)) << 4) + cb * 2) = packbf(v10, v11);
        }
    }
}

// ---------------- 4) barrier-free split-KV flash attention ----------------
// Unit = (64-row Q-tile, 1024 keys = 16 chunks of 64). Q in regs via LDG.
// K/V arrive via cp.async.bulk into ring-3 smem slots, tracked by full/empty
// mbarriers. NO __syncthreads in the mainloop -> warps drift and overlap phases.
__global__ void __launch_bounds__(128, 2) k_attn() {
    extern __shared__ __align__(1024) char smem[];
    uint32_t sb = sptr(smem);
    uint32_t mbF = sb + 98304;          // full[3] @ +0,8,16
    uint32_t mbE = sb + 98304 + 24;     // empty[3]
    int tid = threadIdx.x, wid = tid >> 5, lane = tid & 31;
    int agrp = lane >> 3, lr = lane & 7;

    int u = NU - 1 - (int)blockIdx.x;
    int f = 0;
#pragma unroll
    for (int i = 0; i < 16; i++) if (u >= cU2[i + 1]) f = i + 1;
    int r   = u - cU2[f];
    int ns  = f + 1;
    int tif = r / ns;
    int sp  = r - tif * ns;
    int q0  = (f * 16 + tif) * 64;
    int kc0 = sp * 16;                  // 16 chunks of 64 keys

    // Q -> registers (standard m16k16 A-fragment mapping)
    uint32_t qf[8][4];
    {
        const __nv_bfloat16* qp = g_q + (size_t)(q0 + wid * 16 + (lane >> 2)) * 128
                                  + (lane & 3) * 2;
#pragma unroll
        for (int kk = 0; kk < 8; kk++) {
            qf[kk][0] = *reinterpret_cast<const uint32_t*>(qp + kk * 16);
            qf[kk][1] = *reinterpret_cast<const uint32_t*>(qp + kk * 16 + 8 * 128);
            qf[kk][2] = *reinterpret_cast<const uint32_t*>(qp + kk * 16 + 8);
            qf[kk][3] = *reinterpret_cast<const uint32_t*>(qp + kk * 16 + 8 + 8 * 128);
        }
    }

    if (tid == 0) {
#pragma unroll
        for (int s = 0; s < 3; s++) {
            mbar_init(mbF + 8 * s, 1);   // completes via expect_tx
            mbar_init(mbE + 8 * s, 4);   // one arrival per warp
        }
    }
    __syncthreads();                     // the only block barrier

    if (wid == 0 && elect1()) {          // prologue: fill slots 0..2
#pragma unroll
        for (int s = 0; s < 3; s++) {
            mbar_expect(mbF + 8 * s, 32768);
            bulk_g2s(sb + s * 32768,        (const char*)g_k + (size_t)(kc0 + s) * 16384,
                     16384, mbF + 8 * s);
            bulk_g2s(sb + s * 32768 + 16384,(const char*)g_v + (size_t)(kc0 + s) * 16384,
                     16384, mbF + 8 * s);
        }
    }

    float o[16][4];
#pragma unroll
    for (int j = 0; j < 16; j++) { o[j][0] = o[j][1] = o[j][2] = o[j][3] = 0.f; }
    float l0 = 0.f, l1 = 0.f;

    for (int i = 0; i < 16; i++) {
        int sl = i % 3;
        uint32_t ph = (i / 3) & 1;
        mbar_wait(mbF + 8 * sl, ph);            // chunk i resident (acquire)
        uint32_t kb = sb + sl * 32768, vb = kb + 16384;

        // ---- S = Q @ K^T : 16 rows x 64 keys ----
        float s[8][4];
#pragma unroll
        for (int nt = 0; nt < 8; nt++) { s[nt][0] = s[nt][1] = s[nt][2] = s[nt][3] = 0.f; }
#pragma unroll
        for (int kk2 = 0; kk2 < 4; kk2++) {
#pragma unroll
            for (int nt = 0; nt < 8; nt++) {
                uint32_t b[4];
                ldsm4(b, kb + sw_off(nt * 8 + lr, 4 * kk2 + agrp));
                mma16816(s[nt], qf[2 * kk2],     b);
                mma16816(s[nt], qf[2 * kk2 + 1], b + 2);
            }
        }
        // ---- fixed-max softmax -> bf16 A-fragments ----
        uint32_t pf[4][4];
#pragma unroll
        for (int nt = 0; nt < 8; nt++) {
            float p0 = ex2(s[nt][0]);
            float p1 = ex2(s[nt][1]);
            float p2 = ex2(s[nt][2]);
            float p3 = ex2(s[nt][3]);
            l0 += p0 + p1;  l1 += p2 + p3;
            int kk = nt >> 1;
            if ((nt & 1) == 0) { pf[kk][0] = packbf(p0, p1); pf[kk][1] = packbf(p2, p3); }
            else               { pf[kk][2] = packbf(p0, p1); pf[kk][3] = packbf(p2, p3); }
        }
        // ---- O += P @ V ----
#pragma unroll
        for (int kk2 = 0; kk2 < 2; kk2++) {
#pragma unroll
            for (int j = 0; j < 16; j++) {
                uint32_t vv[4];
                ldsm4t(vv, vb + sw_off(kk2 * 32 + agrp * 8 + lr, j));
                mma16816(o[j], pf[2 * kk2],     vv);
                mma16816(o[j], pf[2 * kk2 + 1], vv + 2);
            }
        }

        if (elect1()) mbar_arrive(mbE + 8 * sl);   // this warp done with slot
        if (wid == 0 && i + 3 < 16 && elect1()) {  // refill slot for chunk i+3
            mbar_wait(mbE + 8 * sl, (i / 3) & 1);  // all 4 warps done with chunk i
            mbar_expect(mbF + 8 * sl, 32768);
            bulk_g2s(kb, (const char*)g_k + (size_t)(kc0 + i + 3) * 16384, 16384, mbF + 8 * sl);
            bulk_g2s(vb, (const char*)g_v + (size_t)(kc0 + i + 3) * 16384, 16384, mbF + 8 * sl);
        }
    }

    // ---- epilogue: quad-reduce l, store unnormalized partials (bf16) ----
    l0 += __shfl_xor_sync(0xffffffffu, l0, 1);
    l0 += __shfl_xor_sync(0xffffffffu, l0, 2);
    l1 += __shfl_xor_sync(0xffffffffu, l1, 1);
    l1 += __shfl_xor_sync(0xffffffffu, l1, 2);
    int lr0 = wid * 16 + (lane >> 2);
    int cb  = (lane & 3) * 2;
    __nv_bfloat16* po = g_po + (size_t)u * 8192;
#pragma unroll
    for (int j = 0; j < 16; j++) {
        int col = j * 8 + cb;
        *reinterpret_cast<uint32_t*>(po + (size_t)lr0 * 128 + col)       = packbf(o[j][0], o[j][1]);
        *reinterpret_cast<uint32_t*>(po + (size_t)(lr0 + 8) * 128 + col) = packbf(o[j][2], o[j][3]);
    }
    if ((lane & 3) == 0) {
        g_pl[u * 64 + lr0]     = l0;
        g_pl[u * 64 + lr0 + 8] = l1;
    }
}

// ---------------- 4b) combine (plain sums over bf16 partials) ----------------
__global__ void __launch_bounds__(256) k_comb() {
    int t  = blockIdx.x;
    int f  = t >> 4;
    int ns = f + 1;
    int ub = cU2[f] + (t & 15) * ns;
    int row = threadIdx.x >> 2;
    int c0  = (threadIdx.x & 3) * 32;
    float l = 0.f;
    for (int s = 0; s < ns; s++) l += g_pl[(ub + s) * 64 + row];
    float inv = 1.f / l;
    float acc[32];
#pragma unroll
    for (int j = 0; j < 32; j++) acc[j] = 0.f;
    for (int s = 0; s < ns; s++) {
        const __nv_bfloat162* p = reinterpret_cast<const __nv_bfloat162*>(
            g_po + (size_t)(ub + s) * 8192 + (size_t)row * 128 + c0);
#pragma unroll
        for (int j = 0; j < 16; j++) {
            float2 v = __bfloat1622float2(p[j]);
            acc[2 * j] += v.x;  acc[2 * j + 1] += v.y;
        }
    }
    __nv_bfloat162* dst = reinterpret_cast<__nv_bfloat162*>(
        g_at + (size_t)(t * 64 + row) * 128 + c0);
#pragma unroll
    for (int j = 0; j < 16; j++)
        dst[j] = __floats2bfloat162_rn(acc[2 * j] * inv, acc[2 * j + 1] * inv);
}

// ---------------- 5) output projection + bias + residual ----------------
__global__ void __launch_bounds__(256) k_oproj(const float* __restrict__ bo,
                                               const float* __restrict__ x,
                                               float* __restrict__ out) {
    extern __shared__ __align__(1024) char smem[];
    uint32_t sA = sptr(smem), sB = sA + 128 * 256;
    int tid = threadIdx.x, wid = tid >> 5, lane = tid & 31;
    load_tile<128, 256>(sA, g_at + blockIdx.x * 128 * 128, tid);
    load_tile<128, 256>(sB, g_wt[3], tid);
    cp_commit(); cp_wait<0>(); __syncthreads();
    int agrp = lane >> 3, lr = lane & 7;
    int mrow = wid * 16 + lr + ((agrp & 1) << 3);
    float acc[16][4];
#pragma unroll
    for (int i = 0; i < 16; i++) { acc[i][0] = acc[i][1] = acc[i][2] = acc[i][3] = 0.f; }
#pragma unroll
    for (int kk2 = 0; kk2 < 4; kk2++) {
        uint32_t a0[4], a1[4];
        ldsm4(a0, sA + sw_off(mrow, 4 * kk2 +     (agrp >> 1)));
        ldsm4(a1, sA + sw_off(mrow, 4 * kk2 + 2 + (agrp >> 1)));
#pragma unroll
        for (int nt = 0; nt < 16; nt++) {
            uint32_t b[4];
            ldsm4(b, sB + sw_off(nt * 8 + lr, 4 * kk2 + agrp));
            mma16816(acc[nt], a0, b);
            mma16816(acc[nt], a1, b + 2);
        }
    }
    int r0 = blockIdx.x * 128 + wid * 16 + (lane >> 2);
    int cb = (lane & 3) * 2;
#pragma unroll
    for (int nt = 0; nt < 16; nt++) {
        int col = nt * 8 + cb;
        float b0 = bo[col], b1 = bo[col + 1];
        *reinterpret_cast<float2*>(out + r0 * 128 + col) =
            make_float2(acc[nt][0] + b0 + x[r0 * 128 + col],
                        acc[nt][1] + b1 + x[r0 * 128 + col + 1]);
        *reinterpret_cast<float2*>(out + (r0 + 8) * 128 + col) =
            make_float2(acc[nt][2] + b0 + x[(r0 + 8) * 128 + col],
                        acc[nt][3] + b1 + x[(r0 + 8) * 128 + col + 1]);
    }
}

// ---------------- launch ----------------
extern "C" void kernel_launch(void* const* d_in, const int* in_sizes, int n_in,
                              void* d_out, int out_size) {
    (void)in_sizes; (void)n_in; (void)out_size;
    const float* x     = (const float*)d_in[0];
    const float* gamma = (const float*)d_in[1];
    const float* wq = (const float*)d_in[2];
    const float* bq = (const float*)d_in[3];
    const float* wk = (const float*)d_in[4];
    const float* bk = (const float*)d_in[5];
    const float* wv = (const float*)d_in[6];
    const float* bv = (const float*)d_in[7];
    const float* wo = (const float*)d_in[8];
    const float* bo = (const float*)d_in[9];
    float* out = (float*)d_out;

    cudaFuncSetAttribute(k_qkv,   cudaFuncAttributeMaxDynamicSharedMemorySize, 65536);
    cudaFuncSetAttribute(k_oproj, cudaFuncAttributeMaxDynamicSharedMemorySize, 65536);
    cudaFuncSetAttribute(k_attn,  cudaFuncAttributeMaxDynamicSharedMemorySize, SM_ATTN);

    k_norm <<<S / 8, 256>>>(x, gamma);
    k_wconv<<<dim3(64, 4), 256>>>(wq, wk, wv, wo);
    k_qkv  <<<dim3(S / 128, 3), 256, 65536>>>(bq, bk, bv);
    k_attn <<<NU, 128, SM_ATTN>>>();
    k_comb <<<256, 256>>>();
    k_oproj<<<S / 128, 256, 65536>>>(bo, x, out);
}